// round 13
// baseline (speedup 1.0000x reference)
#include <cuda_runtime.h>
#include <cuda_bf16.h>
#include <cstdint>

#define NN 10000
#define EE 160000
#define FF 512
#define BM 128
#define BN 128
#define BK 16
#define NT 32               // 512/16 k-tiles
#define TILE_B 4096         // bytes per smem tile (128 rows x 32B)
#define NSTG 3              // cp.async pipeline stages
#define XSZ (NN * FF)

// ---------------- scratch (__device__ globals; no allocs) ----------------
__device__ __align__(16) float g_B[NN * FF];
__device__ __align__(16) __nv_bfloat16 g_Xhi[2 * XSZ];   // ping-pong slices
__device__ __align__(16) __nv_bfloat16 g_Xlo[2 * XSZ];
__device__ __align__(16) __nv_bfloat16 g_Wthi[FF * FF];  // transposed: [n][k]
__device__ __align__(16) __nv_bfloat16 g_Wtlo[FF * FF];
__device__ float g_dis[NN];
__device__ int   g_deg[NN];
__device__ int   g_rowptr[NN + 1];
__device__ int   g_cur[NN];
__device__ int   g_srcidx[EE];
__device__ float g_ew[EE];
__device__ int   g_is64;

__device__ __forceinline__ uint32_t stu32(const void* p) {
    uint32_t a;
    asm("{ .reg .u64 t; cvta.to.shared.u64 t, %1; cvt.u32.u64 %0, t; }" : "=r"(a) : "l"(p));
    return a;
}

// swizzled byte offset of (row r, 16B-chunk c) in a [rows x 16] bf16 tile
__device__ __forceinline__ uint32_t tswz(int r, int c) {
    return (uint32_t)((r * 32 + c * 16) ^ (((r >> 2) & 7) << 4));
}

// ---------------- detect edge dtype + zero degree (fused) ----------------
__global__ void __launch_bounds__(256) k_detect(const int* __restrict__ ei32) {
    if (blockIdx.x < 40) {
        int i = blockIdx.x * 256 + threadIdx.x;
        if (i < NN) g_deg[i] = 0;
        return;
    }
    __shared__ int red[256];
    int t = threadIdx.x;
    int acc = 0;
    for (int w = 1 + 2 * t; w < 4096; w += 512) acc |= ei32[w];
    red[t] = acc;
    __syncthreads();
    for (int off = 128; off > 0; off >>= 1) {
        if (t < off) red[t] |= red[t + off];
        __syncthreads();
    }
    if (t == 0) g_is64 = (red[0] == 0) ? 1 : 0;
}

__device__ __forceinline__ int edge_at(const void* ei, int idx) {
    if (g_is64) return (int)((const long long*)ei)[idx];
    return ((const int*)ei)[idx];
}

// ---------------- degree accumulate ----------------
__global__ void k_deg_acc(const void* __restrict__ ei) {
    int e = blockIdx.x * 256 + threadIdx.x;
    if (e >= EE) return;
    int c = edge_at(ei, EE + e);
    if ((unsigned)c < NN) atomicAdd(&g_deg[c], 1);
}

// ---------------- scan: thread-serial x10 + one block shuffle scan ----------------
__global__ void __launch_bounds__(1024) k_scan() {
    __shared__ int wsum[32];
    const int t = threadIdx.x, lane = t & 31, w = t >> 5;
    const int i0 = t * 10;
    int loc[10];
    int tot = 0;
#pragma unroll
    for (int q = 0; q < 10; q++) {
        int i = i0 + q;
        int v = (i < NN) ? g_deg[i] : 0;
        loc[q] = tot;
        tot += v;
    }
    int s = tot;
#pragma unroll
    for (int o = 1; o < 32; o <<= 1) {
        int x = __shfl_up_sync(0xFFFFFFFFu, s, o);
        if (lane >= o) s += x;
    }
    if (lane == 31) wsum[w] = s;
    __syncthreads();
    if (w == 0) {
        int ws = wsum[lane];
#pragma unroll
        for (int o = 1; o < 32; o <<= 1) {
            int x = __shfl_up_sync(0xFFFFFFFFu, ws, o);
            if (lane >= o) ws += x;
        }
        wsum[lane] = ws;
    }
    __syncthreads();
    int base = (w > 0 ? wsum[w - 1] : 0) + s - tot;
#pragma unroll
    for (int q = 0; q < 10; q++) {
        int i = i0 + q;
        if (i < NN) {
            int excl = base + loc[q];
            g_rowptr[i] = excl;
            g_cur[i] = excl;
            g_dis[i] = rsqrtf(1.0f + (float)g_deg[i]);
        }
    }
    if (t == 1023) g_rowptr[NN] = base + tot;
}

// ---------------- CSR fill ----------------
__global__ void k_fill(const void* __restrict__ ei) {
    int e = blockIdx.x * 256 + threadIdx.x;
    if (e >= EE) return;
    int r = edge_at(ei, e);
    int c = edge_at(ei, EE + e);
    if ((unsigned)r >= NN || (unsigned)c >= NN) return;
    int pos = atomicAdd(&g_cur[c], 1);
    if ((unsigned)pos < EE) {
        g_srcidx[pos] = r;
        g_ew[pos] = g_dis[r] * g_dis[c];
    }
}

// ---------------- fp32 -> bf16 hi/lo split of the input x into slice 0 ----------------
__global__ void __launch_bounds__(256) k_cvt_x(const float* __restrict__ src) {
    int idx = blockIdx.x * 256 + threadIdx.x;
    if (idx >= NN * FF / 4) return;
    float4 v = ((const float4*)src)[idx];
    __nv_bfloat16 h0 = __float2bfloat16(v.x), h1 = __float2bfloat16(v.y);
    __nv_bfloat16 h2 = __float2bfloat16(v.z), h3 = __float2bfloat16(v.w);
    __nv_bfloat16 l0 = __float2bfloat16(v.x - __bfloat162float(h0));
    __nv_bfloat16 l1 = __float2bfloat16(v.y - __bfloat162float(h1));
    __nv_bfloat16 l2 = __float2bfloat16(v.z - __bfloat162float(h2));
    __nv_bfloat16 l3 = __float2bfloat16(v.w - __bfloat162float(h3));
    __nv_bfloat162* ph = (__nv_bfloat162*)(g_Xhi + (size_t)idx * 4);
    __nv_bfloat162* pl = (__nv_bfloat162*)(g_Xlo + (size_t)idx * 4);
    ph[0] = __nv_bfloat162(h0, h1); ph[1] = __nv_bfloat162(h2, h3);
    pl[0] = __nv_bfloat162(l0, l1); pl[1] = __nv_bfloat162(l2, l3);
}

// ---------------- weight transpose + hi/lo split: Wt[n][k] = W[k][n] ----------------
__global__ void __launch_bounds__(256) k_cvt_w(const float* __restrict__ W) {
    __shared__ float tile[32][33];
    int tx = threadIdx.x & 31, ty = threadIdx.x >> 5;
    int bn = blockIdx.x * 32, bk = blockIdx.y * 32;
    for (int r = ty; r < 32; r += 8)
        tile[r][tx] = W[(size_t)(bk + r) * FF + bn + tx];
    __syncthreads();
    for (int r = ty; r < 32; r += 8) {
        float v = tile[tx][r];
        __nv_bfloat16 h = __float2bfloat16(v);
        g_Wthi[(size_t)(bn + r) * FF + bk + tx] = h;
        g_Wtlo[(size_t)(bn + r) * FF + bk + tx] = __float2bfloat16(v - __bfloat162float(h));
    }
}

// ---------------- fused split-bf16 GEMM: g_B = Xhi*Whi + Xhi*Wlo + Xlo*Whi ----------------
// BM=BN=128, 256 threads, 3-stage cp.async pipeline. nblk0 = column-half offset, xsel = X slice.
__global__ void __launch_bounds__(256) k_gemm_mma(int nblk0, int xsel) {
    __shared__ __align__(16) __nv_bfloat16 sm[NSTG][4][2048];

    const int tid = threadIdx.x;
    const int lane = tid & 31, wid = tid >> 5;
    const int n0 = (nblk0 + blockIdx.x) * BN, m0 = blockIdx.y * BM;
    const int mbase = (wid >> 2) * 64, nbase = (wid & 3) * 32;
    const uint32_t smb = stu32(sm);
    const __nv_bfloat16* Xhi = g_Xhi + (size_t)xsel * XSZ;
    const __nv_bfloat16* Xlo = g_Xlo + (size_t)xsel * XSZ;

    float d[4][4][4];
#pragma unroll
    for (int i = 0; i < 4; i++)
#pragma unroll
        for (int j = 0; j < 4; j++)
#pragma unroll
            for (int q = 0; q < 4; q++) d[i][j][q] = 0.0f;

    const int lrow = tid >> 1, lch = tid & 1;  // loader mapping
    auto load_tiles = [&](int it, int stg) {
        const int kb = it * BK;
        uint32_t dst = smb + stg * (4 * TILE_B) + tswz(lrow, lch);
        const size_t xoff = (size_t)(m0 + lrow) * FF + kb + lch * 8;
        const size_t woff = (size_t)(n0 + lrow) * FF + kb + lch * 8;
        int szx = (m0 + lrow) < NN ? 16 : 0;
        asm volatile("cp.async.cg.shared.global [%0], [%1], 16, %2;"
                     :: "r"(dst + 0 * TILE_B), "l"((const void*)(Xhi + xoff)), "r"(szx));
        asm volatile("cp.async.cg.shared.global [%0], [%1], 16, %2;"
                     :: "r"(dst + 1 * TILE_B), "l"((const void*)(Xlo + xoff)), "r"(szx));
        asm volatile("cp.async.cg.shared.global [%0], [%1], 16;"
                     :: "r"(dst + 2 * TILE_B), "l"((const void*)(g_Wthi + woff)));
        asm volatile("cp.async.cg.shared.global [%0], [%1], 16;"
                     :: "r"(dst + 3 * TILE_B), "l"((const void*)(g_Wtlo + woff)));
        asm volatile("cp.async.commit_group;" ::: "memory");
    };

    load_tiles(0, 0);
    load_tiles(1, 1);

    const int frow = lane & 15, fch = lane >> 4;   // fragment lane mapping
    for (int it = 0; it < NT; it++) {
        const int stg = it % NSTG;
        if (it + 2 < NT) {
            load_tiles(it + 2, (it + 2) % NSTG);
            asm volatile("cp.async.wait_group 2;" ::: "memory");
        } else if (it + 1 < NT) {
            asm volatile("cp.async.wait_group 1;" ::: "memory");
        } else {
            asm volatile("cp.async.wait_group 0;" ::: "memory");
        }
        __syncthreads();

        const uint32_t base = smb + stg * (4 * TILE_B);
        uint32_t aHi[4][4], aLo[4][4], bHi[4][2], bLo[4][2];
#pragma unroll
        for (int mf = 0; mf < 4; mf++) {
            uint32_t off = tswz(mbase + mf * 16 + frow, fch);
            asm volatile("ldmatrix.sync.aligned.m8n8.x4.shared.b16 {%0,%1,%2,%3}, [%4];"
                         : "=r"(aHi[mf][0]), "=r"(aHi[mf][1]), "=r"(aHi[mf][2]), "=r"(aHi[mf][3])
                         : "r"(base + 0 * TILE_B + off));
            asm volatile("ldmatrix.sync.aligned.m8n8.x4.shared.b16 {%0,%1,%2,%3}, [%4];"
                         : "=r"(aLo[mf][0]), "=r"(aLo[mf][1]), "=r"(aLo[mf][2]), "=r"(aLo[mf][3])
                         : "r"(base + 1 * TILE_B + off));
        }
#pragma unroll
        for (int nb = 0; nb < 2; nb++) {
            uint32_t off = tswz(nbase + nb * 16 + frow, fch);
            uint32_t r0, r1, r2, r3;
            asm volatile("ldmatrix.sync.aligned.m8n8.x4.shared.b16 {%0,%1,%2,%3}, [%4];"
                         : "=r"(r0), "=r"(r1), "=r"(r2), "=r"(r3)
                         : "r"(base + 2 * TILE_B + off));
            bHi[nb * 2][0] = r0; bHi[nb * 2][1] = r2;
            bHi[nb * 2 + 1][0] = r1; bHi[nb * 2 + 1][1] = r3;
            asm volatile("ldmatrix.sync.aligned.m8n8.x4.shared.b16 {%0,%1,%2,%3}, [%4];"
                         : "=r"(r0), "=r"(r1), "=r"(r2), "=r"(r3)
                         : "r"(base + 3 * TILE_B + off));
            bLo[nb * 2][0] = r0; bLo[nb * 2][1] = r2;
            bLo[nb * 2 + 1][0] = r1; bLo[nb * 2 + 1][1] = r3;
        }

#define MMA(A, B, mf, nf)                                                         \
        asm volatile(                                                             \
            "mma.sync.aligned.m16n8k16.row.col.f32.bf16.bf16.f32 "                \
            "{%0,%1,%2,%3}, {%4,%5,%6,%7}, {%8,%9}, {%0,%1,%2,%3};"               \
            : "+f"(d[mf][nf][0]), "+f"(d[mf][nf][1]),                             \
              "+f"(d[mf][nf][2]), "+f"(d[mf][nf][3])                              \
            : "r"(A[mf][0]), "r"(A[mf][1]), "r"(A[mf][2]), "r"(A[mf][3]),         \
              "r"(B[nf][0]), "r"(B[nf][1]))
#pragma unroll
        for (int mf = 0; mf < 4; mf++)
#pragma unroll
            for (int nf = 0; nf < 4; nf++) {
                MMA(aHi, bHi, mf, nf);
                MMA(aHi, bLo, mf, nf);
                MMA(aLo, bHi, mf, nf);
            }
#undef MMA
        __syncthreads();
    }

    // epilogue: write fp32 result to g_B
    const int g = lane >> 2, tg = lane & 3;
#pragma unroll
    for (int mf = 0; mf < 4; mf++) {
        int row0 = m0 + mbase + mf * 16 + g;
        int row1 = row0 + 8;
#pragma unroll
        for (int nf = 0; nf < 4; nf++) {
            int col = n0 + nbase + nf * 8 + tg * 2;
            if (row0 < NN)
                *(float2*)(g_B + (size_t)row0 * FF + col) = make_float2(d[mf][nf][0], d[mf][nf][1]);
            if (row1 < NN)
                *(float2*)(g_B + (size_t)row1 * FF + col) = make_float2(d[mf][nf][2], d[mf][nf][3]);
        }
    }
}

// ---------------- fused aggregation over a 256-column half ----------------
// 64 threads x float4 = 256 cols. mode 1: write bf16 hi/lo into slice xout; mode 0: fp32 out.
__global__ void __launch_bounds__(64) k_agg_h(const float* __restrict__ bias,
                                              int mode, float* __restrict__ extOut,
                                              int col0, int xout) {
    const float* h = g_B;
    __shared__ int   sh_src[64];
    __shared__ float sh_w[64];
    const int i = blockIdx.x;
    const int t = threadIdx.x;

    float dd = g_dis[i];
    float w0 = dd * dd;
    float4 acc = ((const float4*)(h + (size_t)i * FF + col0))[t];
    acc.x *= w0; acc.y *= w0; acc.z *= w0; acc.w *= w0;

    const int s = g_rowptr[i], e2 = g_rowptr[i + 1];
    for (int base = s; base < e2; base += 64) {
        int m = e2 - base;
        if (m > 64) m = 64;
        if (t < m) {
            sh_src[t] = g_srcidx[base + t];
            sh_w[t]   = g_ew[base + t];
        }
        __syncthreads();
#pragma unroll 4
        for (int j = 0; j < m; j++) {
            const float4 v = ((const float4*)(h + (size_t)sh_src[j] * FF + col0))[t];
            const float w = sh_w[j];
            acc.x += v.x * w; acc.y += v.y * w;
            acc.z += v.z * w; acc.w += v.w * w;
        }
        __syncthreads();
    }

    float4 bb = ((const float4*)(bias + col0))[t];
    acc.x += bb.x; acc.y += bb.y; acc.z += bb.z; acc.w += bb.w;

    if (mode) {
        acc.x = fmaxf(acc.x, 0.f); acc.y = fmaxf(acc.y, 0.f);
        acc.z = fmaxf(acc.z, 0.f); acc.w = fmaxf(acc.w, 0.f);
        __nv_bfloat16 h0 = __float2bfloat16(acc.x), h1 = __float2bfloat16(acc.y);
        __nv_bfloat16 h2 = __float2bfloat16(acc.z), h3 = __float2bfloat16(acc.w);
        __nv_bfloat16 l0 = __float2bfloat16(acc.x - __bfloat162float(h0));
        __nv_bfloat16 l1 = __float2bfloat16(acc.y - __bfloat162float(h1));
        __nv_bfloat16 l2 = __float2bfloat16(acc.z - __bfloat162float(h2));
        __nv_bfloat16 l3 = __float2bfloat16(acc.w - __bfloat162float(h3));
        size_t o = (size_t)xout * XSZ + (size_t)i * FF + col0 + t * 4;
        __nv_bfloat162* ph = (__nv_bfloat162*)(g_Xhi + o);
        __nv_bfloat162* pl = (__nv_bfloat162*)(g_Xlo + o);
        ph[0] = __nv_bfloat162(h0, h1); ph[1] = __nv_bfloat162(h2, h3);
        pl[0] = __nv_bfloat162(l0, l1); pl[1] = __nv_bfloat162(l2, l3);
    } else {
        ((float4*)(extOut + (size_t)i * FF + col0))[t] = acc;
    }
}

// ---------------- launcher: fork-join overlap, ping-pong X slices ----------------
extern "C" void kernel_launch(void* const* d_in, const int* in_sizes, int n_in,
                              void* d_out, int out_size) {
    const float* x   = (const float*)d_in[0];
    const void*  ei  = d_in[1];
    const float* W1  = (const float*)d_in[2];
    const float* b1  = (const float*)d_in[3];
    const float* W2  = (const float*)d_in[4];
    const float* b2  = (const float*)d_in[5];
    const float* W3  = (const float*)d_in[6];
    const float* b3  = (const float*)d_in[7];
    float* out       = (float*)d_out;

    dim3 gemm_grid(2, (NN + BM - 1) / BM);   // half the columns per launch
    dim3 cvtw_grid(16, 16);
    int cvtx_blocks = (NN * FF / 4 + 255) / 256;

    cudaStream_t s2;
    cudaEvent_t eva, evb;
    cudaStreamCreateWithFlags(&s2, cudaStreamNonBlocking);
    cudaEventCreateWithFlags(&eva, cudaEventDisableTiming);
    cudaEventCreateWithFlags(&evb, cudaEventDisableTiming);

    // setup: detect+zero -> degree -> scan+dis -> fill
    k_detect<<<41, 256>>>((const int*)ei);
    k_deg_acc<<<(EE + 255) / 256, 256>>>(ei);
    k_scan<<<1, 1024>>>();
    k_fill<<<(EE + 255) / 256, 256>>>(ei);

    const float* Ws[3] = {W1, W2, W3};
    const float* bs[3] = {b1, b2, b3};
    for (int l = 0; l < 3; l++) {
        k_cvt_w<<<cvtw_grid, 256>>>(Ws[l]);
        if (l == 0) k_cvt_x<<<cvtx_blocks, 256>>>(x);
        const int mode = (l < 2) ? 1 : 0;
        float* dst = (l < 2) ? nullptr : out;
        const int xin = l & 1, xout = (l + 1) & 1;   // ping-pong
        // GEMM cols 0-255 (reads X slice xin)
        k_gemm_mma<<<gemm_grid, 256>>>(0, xin);
        cudaEventRecord(eva, 0);
        // GEMM cols 256-511 (main, reads xin) || agg cols 0-255 (s2, writes xout)
        k_gemm_mma<<<gemm_grid, 256>>>(2, xin);
        cudaStreamWaitEvent(s2, eva, 0);
        k_agg_h<<<NN, 64, 0, s2>>>(bs[l], mode, dst, 0, xout);
        cudaEventRecord(evb, s2);
        cudaStreamWaitEvent(0, evb, 0);
        // agg cols 256-511 (main, writes xout)
        k_agg_h<<<NN, 64>>>(bs[l], mode, dst, 256, xout);
    }

    // destroy only when NOT capturing (destroying a captured stream invalidates the graph)
    cudaStreamCaptureStatus st = cudaStreamCaptureStatusNone;
    cudaStreamIsCapturing(0, &st);
    if (st == cudaStreamCaptureStatusNone) {
        cudaStreamDestroy(s2);
        cudaEventDestroy(eva);
        cudaEventDestroy(evb);
    }
}

// round 15
// speedup vs baseline: 1.2229x; 1.2229x over previous
#include <cuda_runtime.h>
#include <cuda_bf16.h>
#include <cstdint>

#define NN 10000
#define EE 160000
#define FF 512
#define BM 128
#define BN 128
#define BK 16
#define NT 32               // 512/16 k-tiles
#define TILE_B 4096         // bytes per smem tile (128 rows x 32B)
#define NSTG 3              // cp.async pipeline stages

// ---------------- scratch (__device__ globals; no allocs) ----------------
__device__ __align__(16) float g_B[NN * FF];
__device__ __align__(16) __nv_bfloat16 g_Xhi[NN * FF];
__device__ __align__(16) __nv_bfloat16 g_Xlo[NN * FF];
__device__ __align__(16) __nv_bfloat16 g_Wthi[2 * FF * FF];   // double-buffered: [slot][n][k]
__device__ __align__(16) __nv_bfloat16 g_Wtlo[2 * FF * FF];
__device__ float g_dis[NN];
__device__ int   g_deg[NN];
__device__ int   g_rowptr[NN + 1];
__device__ int   g_cur[NN];
__device__ int   g_srcidx[EE];
__device__ float g_ew[EE];
__device__ int   g_is64;

__device__ __forceinline__ uint32_t stu32(const void* p) {
    uint32_t a;
    asm("{ .reg .u64 t; cvta.to.shared.u64 t, %1; cvt.u32.u64 %0, t; }" : "=r"(a) : "l"(p));
    return a;
}

// swizzled byte offset of (row r, 16B-chunk c) in a [rows x 16] bf16 tile
__device__ __forceinline__ uint32_t tswz(int r, int c) {
    return (uint32_t)((r * 32 + c * 16) ^ (((r >> 2) & 7) << 4));
}

// ---------------- detect edge dtype + zero degree (fused) ----------------
__global__ void __launch_bounds__(256) k_detect(const int* __restrict__ ei32) {
    if (blockIdx.x < 40) {
        int i = blockIdx.x * 256 + threadIdx.x;
        if (i < NN) g_deg[i] = 0;
        return;
    }
    __shared__ int red[256];
    int t = threadIdx.x;
    int acc = 0;
    for (int w = 1 + 2 * t; w < 4096; w += 512) acc |= ei32[w];
    red[t] = acc;
    __syncthreads();
    for (int off = 128; off > 0; off >>= 1) {
        if (t < off) red[t] |= red[t + off];
        __syncthreads();
    }
    if (t == 0) g_is64 = (red[0] == 0) ? 1 : 0;
}

__device__ __forceinline__ int edge_at(const void* ei, int idx) {
    if (g_is64) return (int)((const long long*)ei)[idx];
    return ((const int*)ei)[idx];
}

// ---------------- degree accumulate ----------------
__global__ void k_deg_acc(const void* __restrict__ ei) {
    int e = blockIdx.x * 256 + threadIdx.x;
    if (e >= EE) return;
    int c = edge_at(ei, EE + e);
    if ((unsigned)c < NN) atomicAdd(&g_deg[c], 1);
}

// ---------------- scan: thread-serial x10 + one block shuffle scan ----------------
__global__ void __launch_bounds__(1024) k_scan() {
    __shared__ int wsum[32];
    const int t = threadIdx.x, lane = t & 31, w = t >> 5;
    const int i0 = t * 10;
    int loc[10];
    int tot = 0;
#pragma unroll
    for (int q = 0; q < 10; q++) {
        int i = i0 + q;
        int v = (i < NN) ? g_deg[i] : 0;
        loc[q] = tot;
        tot += v;
    }
    int s = tot;
#pragma unroll
    for (int o = 1; o < 32; o <<= 1) {
        int x = __shfl_up_sync(0xFFFFFFFFu, s, o);
        if (lane >= o) s += x;
    }
    if (lane == 31) wsum[w] = s;
    __syncthreads();
    if (w == 0) {
        int ws = wsum[lane];
#pragma unroll
        for (int o = 1; o < 32; o <<= 1) {
            int x = __shfl_up_sync(0xFFFFFFFFu, ws, o);
            if (lane >= o) ws += x;
        }
        wsum[lane] = ws;
    }
    __syncthreads();
    int base = (w > 0 ? wsum[w - 1] : 0) + s - tot;
#pragma unroll
    for (int q = 0; q < 10; q++) {
        int i = i0 + q;
        if (i < NN) {
            int excl = base + loc[q];
            g_rowptr[i] = excl;
            g_cur[i] = excl;
            g_dis[i] = rsqrtf(1.0f + (float)g_deg[i]);
        }
    }
    if (t == 1023) g_rowptr[NN] = base + tot;
}

// ---------------- CSR fill ----------------
__global__ void k_fill(const void* __restrict__ ei) {
    int e = blockIdx.x * 256 + threadIdx.x;
    if (e >= EE) return;
    int r = edge_at(ei, e);
    int c = edge_at(ei, EE + e);
    if ((unsigned)r >= NN || (unsigned)c >= NN) return;
    int pos = atomicAdd(&g_cur[c], 1);
    if ((unsigned)pos < EE) {
        g_srcidx[pos] = r;
        g_ew[pos] = g_dis[r] * g_dis[c];
    }
}

// ---------------- fp32 -> bf16 hi/lo split of the input x ----------------
__global__ void __launch_bounds__(256) k_cvt_x(const float* __restrict__ src) {
    int idx = blockIdx.x * 256 + threadIdx.x;
    if (idx >= NN * FF / 4) return;
    float4 v = ((const float4*)src)[idx];
    __nv_bfloat16 h0 = __float2bfloat16(v.x), h1 = __float2bfloat16(v.y);
    __nv_bfloat16 h2 = __float2bfloat16(v.z), h3 = __float2bfloat16(v.w);
    __nv_bfloat16 l0 = __float2bfloat16(v.x - __bfloat162float(h0));
    __nv_bfloat16 l1 = __float2bfloat16(v.y - __bfloat162float(h1));
    __nv_bfloat16 l2 = __float2bfloat16(v.z - __bfloat162float(h2));
    __nv_bfloat16 l3 = __float2bfloat16(v.w - __bfloat162float(h3));
    __nv_bfloat162* ph = (__nv_bfloat162*)(g_Xhi + (size_t)idx * 4);
    __nv_bfloat162* pl = (__nv_bfloat162*)(g_Xlo + (size_t)idx * 4);
    ph[0] = __nv_bfloat162(h0, h1); ph[1] = __nv_bfloat162(h2, h3);
    pl[0] = __nv_bfloat162(l0, l1); pl[1] = __nv_bfloat162(l2, l3);
}

// ---------------- weight transpose + hi/lo split into weight slot ----------------
__global__ void __launch_bounds__(256) k_cvt_w(const float* __restrict__ W, int slot) {
    __shared__ float tile[32][33];
    const size_t wb = (size_t)slot * FF * FF;
    int tx = threadIdx.x & 31, ty = threadIdx.x >> 5;
    int bn = blockIdx.x * 32, bk = blockIdx.y * 32;
    for (int r = ty; r < 32; r += 8)
        tile[r][tx] = W[(size_t)(bk + r) * FF + bn + tx];
    __syncthreads();
    for (int r = ty; r < 32; r += 8) {
        float v = tile[tx][r];
        __nv_bfloat16 h = __float2bfloat16(v);
        g_Wthi[wb + (size_t)(bn + r) * FF + bk + tx] = h;
        g_Wtlo[wb + (size_t)(bn + r) * FF + bk + tx] = __float2bfloat16(v - __bfloat162float(h));
    }
}

// ---------------- fused split-bf16 GEMM: g_B = Xhi*Whi + Xhi*Wlo + Xlo*Whi ----------------
// BM=BN=128, 256 threads, 3-stage cp.async pipeline.  (R8 configuration)
__global__ void __launch_bounds__(256) k_gemm_mma(int wslot) {
    __shared__ __align__(16) __nv_bfloat16 sm[NSTG][4][2048];

    const int tid = threadIdx.x;
    const int lane = tid & 31, wid = tid >> 5;
    const int n0 = blockIdx.x * BN, m0 = blockIdx.y * BM;
    const int mbase = (wid >> 2) * 64, nbase = (wid & 3) * 32;
    const uint32_t smb = stu32(sm);
    const __nv_bfloat16* Whi = g_Wthi + (size_t)wslot * FF * FF;
    const __nv_bfloat16* Wlo = g_Wtlo + (size_t)wslot * FF * FF;

    float d[4][4][4];
#pragma unroll
    for (int i = 0; i < 4; i++)
#pragma unroll
        for (int j = 0; j < 4; j++)
#pragma unroll
            for (int q = 0; q < 4; q++) d[i][j][q] = 0.0f;

    const int lrow = tid >> 1, lch = tid & 1;  // loader mapping
    auto load_tiles = [&](int it, int stg) {
        const int kb = it * BK;
        uint32_t dst = smb + stg * (4 * TILE_B) + tswz(lrow, lch);
        const size_t xoff = (size_t)(m0 + lrow) * FF + kb + lch * 8;
        const size_t woff = (size_t)(n0 + lrow) * FF + kb + lch * 8;
        int szx = (m0 + lrow) < NN ? 16 : 0;
        asm volatile("cp.async.cg.shared.global [%0], [%1], 16, %2;"
                     :: "r"(dst + 0 * TILE_B), "l"((const void*)(g_Xhi + xoff)), "r"(szx));
        asm volatile("cp.async.cg.shared.global [%0], [%1], 16, %2;"
                     :: "r"(dst + 1 * TILE_B), "l"((const void*)(g_Xlo + xoff)), "r"(szx));
        asm volatile("cp.async.cg.shared.global [%0], [%1], 16;"
                     :: "r"(dst + 2 * TILE_B), "l"((const void*)(Whi + woff)));
        asm volatile("cp.async.cg.shared.global [%0], [%1], 16;"
                     :: "r"(dst + 3 * TILE_B), "l"((const void*)(Wlo + woff)));
        asm volatile("cp.async.commit_group;" ::: "memory");
    };

    load_tiles(0, 0);
    load_tiles(1, 1);

    const int frow = lane & 15, fch = lane >> 4;   // fragment lane mapping
    for (int it = 0; it < NT; it++) {
        const int stg = it % NSTG;
        if (it + 2 < NT) {
            load_tiles(it + 2, (it + 2) % NSTG);
            asm volatile("cp.async.wait_group 2;" ::: "memory");
        } else if (it + 1 < NT) {
            asm volatile("cp.async.wait_group 1;" ::: "memory");
        } else {
            asm volatile("cp.async.wait_group 0;" ::: "memory");
        }
        __syncthreads();

        const uint32_t base = smb + stg * (4 * TILE_B);
        uint32_t aHi[4][4], aLo[4][4], bHi[4][2], bLo[4][2];
#pragma unroll
        for (int mf = 0; mf < 4; mf++) {
            uint32_t off = tswz(mbase + mf * 16 + frow, fch);
            asm volatile("ldmatrix.sync.aligned.m8n8.x4.shared.b16 {%0,%1,%2,%3}, [%4];"
                         : "=r"(aHi[mf][0]), "=r"(aHi[mf][1]), "=r"(aHi[mf][2]), "=r"(aHi[mf][3])
                         : "r"(base + 0 * TILE_B + off));
            asm volatile("ldmatrix.sync.aligned.m8n8.x4.shared.b16 {%0,%1,%2,%3}, [%4];"
                         : "=r"(aLo[mf][0]), "=r"(aLo[mf][1]), "=r"(aLo[mf][2]), "=r"(aLo[mf][3])
                         : "r"(base + 1 * TILE_B + off));
        }
#pragma unroll
        for (int nb = 0; nb < 2; nb++) {
            uint32_t off = tswz(nbase + nb * 16 + frow, fch);
            uint32_t r0, r1, r2, r3;
            asm volatile("ldmatrix.sync.aligned.m8n8.x4.shared.b16 {%0,%1,%2,%3}, [%4];"
                         : "=r"(r0), "=r"(r1), "=r"(r2), "=r"(r3)
                         : "r"(base + 2 * TILE_B + off));
            bHi[nb * 2][0] = r0; bHi[nb * 2][1] = r2;
            bHi[nb * 2 + 1][0] = r1; bHi[nb * 2 + 1][1] = r3;
            asm volatile("ldmatrix.sync.aligned.m8n8.x4.shared.b16 {%0,%1,%2,%3}, [%4];"
                         : "=r"(r0), "=r"(r1), "=r"(r2), "=r"(r3)
                         : "r"(base + 3 * TILE_B + off));
            bLo[nb * 2][0] = r0; bLo[nb * 2][1] = r2;
            bLo[nb * 2 + 1][0] = r1; bLo[nb * 2 + 1][1] = r3;
        }

#define MMA(A, B, mf, nf)                                                         \
        asm volatile(                                                             \
            "mma.sync.aligned.m16n8k16.row.col.f32.bf16.bf16.f32 "                \
            "{%0,%1,%2,%3}, {%4,%5,%6,%7}, {%8,%9}, {%0,%1,%2,%3};"               \
            : "+f"(d[mf][nf][0]), "+f"(d[mf][nf][1]),                             \
              "+f"(d[mf][nf][2]), "+f"(d[mf][nf][3])                              \
            : "r"(A[mf][0]), "r"(A[mf][1]), "r"(A[mf][2]), "r"(A[mf][3]),         \
              "r"(B[nf][0]), "r"(B[nf][1]))
#pragma unroll
        for (int mf = 0; mf < 4; mf++)
#pragma unroll
            for (int nf = 0; nf < 4; nf++) {
                MMA(aHi, bHi, mf, nf);
                MMA(aHi, bLo, mf, nf);
                MMA(aLo, bHi, mf, nf);
            }
#undef MMA
        __syncthreads();
    }

    // epilogue: write fp32 result to g_B
    const int g = lane >> 2, tg = lane & 3;
#pragma unroll
    for (int mf = 0; mf < 4; mf++) {
        int row0 = m0 + mbase + mf * 16 + g;
        int row1 = row0 + 8;
#pragma unroll
        for (int nf = 0; nf < 4; nf++) {
            int col = n0 + nbase + nf * 8 + tg * 2;
            if (row0 < NN)
                *(float2*)(g_B + (size_t)row0 * FF + col) = make_float2(d[mf][nf][0], d[mf][nf][1]);
            if (row1 < NN)
                *(float2*)(g_B + (size_t)row1 * FF + col) = make_float2(d[mf][nf][2], d[mf][nf][3]);
        }
    }
}

// ---------------- fused aggregation (R8 exact: smem staging, unroll 4) ----------------
__global__ void __launch_bounds__(128) k_agg(const float* __restrict__ bias,
                                             int mode, float* __restrict__ extOut) {
    const float* h = g_B;
    __shared__ int   sh_src[128];
    __shared__ float sh_w[128];
    const int i = blockIdx.x;
    const int t = threadIdx.x;

    float dd = g_dis[i];
    float w0 = dd * dd;
    float4 acc = ((const float4*)(h + (size_t)i * FF))[t];
    acc.x *= w0; acc.y *= w0; acc.z *= w0; acc.w *= w0;

    const int s = g_rowptr[i], e2 = g_rowptr[i + 1];
    for (int base = s; base < e2; base += 128) {
        int m = e2 - base;
        if (m > 128) m = 128;
        if (t < m) {
            sh_src[t] = g_srcidx[base + t];
            sh_w[t]   = g_ew[base + t];
        }
        __syncthreads();
#pragma unroll 4
        for (int j = 0; j < m; j++) {
            const float4 v = ((const float4*)(h + (size_t)sh_src[j] * FF))[t];
            const float w = sh_w[j];
            acc.x += v.x * w; acc.y += v.y * w;
            acc.z += v.z * w; acc.w += v.w * w;
        }
        __syncthreads();
    }

    float4 bb = ((const float4*)bias)[t];
    acc.x += bb.x; acc.y += bb.y; acc.z += bb.z; acc.w += bb.w;

    if (mode) {
        acc.x = fmaxf(acc.x, 0.f); acc.y = fmaxf(acc.y, 0.f);
        acc.z = fmaxf(acc.z, 0.f); acc.w = fmaxf(acc.w, 0.f);
        __nv_bfloat16 h0 = __float2bfloat16(acc.x), h1 = __float2bfloat16(acc.y);
        __nv_bfloat16 h2 = __float2bfloat16(acc.z), h3 = __float2bfloat16(acc.w);
        __nv_bfloat16 l0 = __float2bfloat16(acc.x - __bfloat162float(h0));
        __nv_bfloat16 l1 = __float2bfloat16(acc.y - __bfloat162float(h1));
        __nv_bfloat16 l2 = __float2bfloat16(acc.z - __bfloat162float(h2));
        __nv_bfloat16 l3 = __float2bfloat16(acc.w - __bfloat162float(h3));
        size_t o = (size_t)i * FF + t * 4;
        __nv_bfloat162* ph = (__nv_bfloat162*)(g_Xhi + o);
        __nv_bfloat162* pl = (__nv_bfloat162*)(g_Xlo + o);
        ph[0] = __nv_bfloat162(h0, h1); ph[1] = __nv_bfloat162(h2, h3);
        pl[0] = __nv_bfloat162(l0, l1); pl[1] = __nv_bfloat162(l2, l3);
    } else {
        ((float4*)(extOut + (size_t)i * FF))[t] = acc;
    }
}

// ---------------- launcher: proper capture fork (s2 joins via event BEFORE any launch) ----------------
extern "C" void kernel_launch(void* const* d_in, const int* in_sizes, int n_in,
                              void* d_out, int out_size) {
    const float* x   = (const float*)d_in[0];
    const void*  ei  = d_in[1];
    const float* W1  = (const float*)d_in[2];
    const float* b1  = (const float*)d_in[3];
    const float* W2  = (const float*)d_in[4];
    const float* b2  = (const float*)d_in[5];
    const float* W3  = (const float*)d_in[6];
    const float* b3  = (const float*)d_in[7];
    float* out       = (float*)d_out;

    dim3 gemm_grid(FF / BN, (NN + BM - 1) / BM);   // (4, 79)
    dim3 cvtw_grid(16, 16);
    int cvtx_blocks = (NN * FF / 4 + 255) / 256;

    cudaStream_t s2;
    cudaEvent_t ev0, ev_g, ev_c;
    cudaStreamCreateWithFlags(&s2, cudaStreamNonBlocking);
    cudaEventCreateWithFlags(&ev0, cudaEventDisableTiming);
    cudaEventCreateWithFlags(&ev_g, cudaEventDisableTiming);
    cudaEventCreateWithFlags(&ev_c, cudaEventDisableTiming);

    // origin stream starts the graph; s2 joins via event BEFORE its first launch
    k_detect<<<41, 256>>>((const int*)ei);
    cudaEventRecord(ev0, 0);
    cudaStreamWaitEvent(s2, ev0, 0);

    // fork: edge/CSR chain on 0  ||  converter chain on s2
    k_deg_acc<<<(EE + 255) / 256, 256>>>(ei);
    k_scan<<<1, 1024>>>();
    k_fill<<<(EE + 255) / 256, 256>>>(ei);

    k_cvt_w<<<cvtw_grid, 256, 0, s2>>>(W1, 0);
    k_cvt_x<<<cvtx_blocks, 256, 0, s2>>>(x);
    cudaEventRecord(ev_c, s2);
    cudaStreamWaitEvent(0, ev_c, 0);   // join

    const float* Ws[3] = {W1, W2, W3};
    const float* bs[3] = {b1, b2, b3};
    for (int l = 0; l < 3; l++) {
        const int slot = l & 1;
        k_gemm_mma<<<gemm_grid, 256>>>(slot);
        if (l < 2) {
            // convert next layer's weights on s2, overlapped with this layer's agg
            cudaEventRecord(ev_g, 0);
            cudaStreamWaitEvent(s2, ev_g, 0);
            k_cvt_w<<<cvtw_grid, 256, 0, s2>>>(Ws[l + 1], slot ^ 1);
            cudaEventRecord(ev_c, s2);
        }
        const int mode = (l < 2) ? 1 : 0;
        float* dst = (l < 2) ? nullptr : out;
        k_agg<<<NN, 128>>>(bs[l], mode, dst);
        if (l < 2) cudaStreamWaitEvent(0, ev_c, 0);
    }

    // destroy only when NOT capturing (destroying a captured stream invalidates the graph)
    cudaStreamCaptureStatus st = cudaStreamCaptureStatusNone;
    cudaStreamIsCapturing(0, &st);
    if (st == cudaStreamCaptureStatusNone) {
        cudaStreamDestroy(s2);
        cudaEventDestroy(ev0);
        cudaEventDestroy(ev_g);
        cudaEventDestroy(ev_c);
    }
}

// round 16
// speedup vs baseline: 1.3990x; 1.1440x over previous
#include <cuda_runtime.h>
#include <cuda_bf16.h>
#include <cstdint>

#define NN 10000
#define EE 160000
#define FF 512
#define BM 64
#define BN 128
#define BK 16
#define NT 32               // 512/16 k-tiles
#define NSTG 3              // cp.async pipeline stages
// per-stage smem (bytes): Ahi 2048 | Alo 2048 | Bhi 4096 | Blo 4096 = 12288
#define A_T 2048
#define B_T 4096
#define STG_B 12288

// ---------------- scratch (__device__ globals; no allocs) ----------------
__device__ __align__(16) float g_B[NN * FF];
__device__ __align__(16) __nv_bfloat16 g_Xhi[NN * FF];
__device__ __align__(16) __nv_bfloat16 g_Xlo[NN * FF];
__device__ __align__(16) __nv_bfloat16 g_Wthi[2 * FF * FF];   // double-buffered: [slot][n][k]
__device__ __align__(16) __nv_bfloat16 g_Wtlo[2 * FF * FF];
__device__ float g_dis[NN];
__device__ int   g_deg[NN];
__device__ int   g_rowptr[NN + 1];
__device__ int   g_cur[NN];
__device__ int   g_srcidx[EE];
__device__ float g_ew[EE];
__device__ int   g_is64;

__device__ __forceinline__ uint32_t stu32(const void* p) {
    uint32_t a;
    asm("{ .reg .u64 t; cvta.to.shared.u64 t, %1; cvt.u32.u64 %0, t; }" : "=r"(a) : "l"(p));
    return a;
}

// swizzled byte offset of (row r, 16B-chunk c) in a [rows x 16] bf16 tile
__device__ __forceinline__ uint32_t tswz(int r, int c) {
    return (uint32_t)((r * 32 + c * 16) ^ (((r >> 2) & 7) << 4));
}

// ---------------- detect edge dtype + zero degree (fused) ----------------
__global__ void __launch_bounds__(256) k_detect(const int* __restrict__ ei32) {
    if (blockIdx.x < 40) {
        int i = blockIdx.x * 256 + threadIdx.x;
        if (i < NN) g_deg[i] = 0;
        return;
    }
    __shared__ int red[256];
    int t = threadIdx.x;
    int acc = 0;
    for (int w = 1 + 2 * t; w < 4096; w += 512) acc |= ei32[w];
    red[t] = acc;
    __syncthreads();
    for (int off = 128; off > 0; off >>= 1) {
        if (t < off) red[t] |= red[t + off];
        __syncthreads();
    }
    if (t == 0) g_is64 = (red[0] == 0) ? 1 : 0;
}

__device__ __forceinline__ int edge_at(const void* ei, int idx) {
    if (g_is64) return (int)((const long long*)ei)[idx];
    return ((const int*)ei)[idx];
}

// ---------------- degree accumulate ----------------
__global__ void k_deg_acc(const void* __restrict__ ei) {
    int e = blockIdx.x * 256 + threadIdx.x;
    if (e >= EE) return;
    int c = edge_at(ei, EE + e);
    if ((unsigned)c < NN) atomicAdd(&g_deg[c], 1);
}

// ---------------- scan: thread-serial x10 + one block shuffle scan ----------------
__global__ void __launch_bounds__(1024) k_scan() {
    __shared__ int wsum[32];
    const int t = threadIdx.x, lane = t & 31, w = t >> 5;
    const int i0 = t * 10;
    int loc[10];
    int tot = 0;
#pragma unroll
    for (int q = 0; q < 10; q++) {
        int i = i0 + q;
        int v = (i < NN) ? g_deg[i] : 0;
        loc[q] = tot;
        tot += v;
    }
    int s = tot;
#pragma unroll
    for (int o = 1; o < 32; o <<= 1) {
        int x = __shfl_up_sync(0xFFFFFFFFu, s, o);
        if (lane >= o) s += x;
    }
    if (lane == 31) wsum[w] = s;
    __syncthreads();
    if (w == 0) {
        int ws = wsum[lane];
#pragma unroll
        for (int o = 1; o < 32; o <<= 1) {
            int x = __shfl_up_sync(0xFFFFFFFFu, ws, o);
            if (lane >= o) ws += x;
        }
        wsum[lane] = ws;
    }
    __syncthreads();
    int base = (w > 0 ? wsum[w - 1] : 0) + s - tot;
#pragma unroll
    for (int q = 0; q < 10; q++) {
        int i = i0 + q;
        if (i < NN) {
            int excl = base + loc[q];
            g_rowptr[i] = excl;
            g_cur[i] = excl;
            g_dis[i] = rsqrtf(1.0f + (float)g_deg[i]);
        }
    }
    if (t == 1023) g_rowptr[NN] = base + tot;
}

// ---------------- CSR fill ----------------
__global__ void k_fill(const void* __restrict__ ei) {
    int e = blockIdx.x * 256 + threadIdx.x;
    if (e >= EE) return;
    int r = edge_at(ei, e);
    int c = edge_at(ei, EE + e);
    if ((unsigned)r >= NN || (unsigned)c >= NN) return;
    int pos = atomicAdd(&g_cur[c], 1);
    if ((unsigned)pos < EE) {
        g_srcidx[pos] = r;
        g_ew[pos] = g_dis[r] * g_dis[c];
    }
}

// ---------------- fp32 -> bf16 hi/lo split of the input x ----------------
__global__ void __launch_bounds__(256) k_cvt_x(const float* __restrict__ src) {
    int idx = blockIdx.x * 256 + threadIdx.x;
    if (idx >= NN * FF / 4) return;
    float4 v = ((const float4*)src)[idx];
    __nv_bfloat16 h0 = __float2bfloat16(v.x), h1 = __float2bfloat16(v.y);
    __nv_bfloat16 h2 = __float2bfloat16(v.z), h3 = __float2bfloat16(v.w);
    __nv_bfloat16 l0 = __float2bfloat16(v.x - __bfloat162float(h0));
    __nv_bfloat16 l1 = __float2bfloat16(v.y - __bfloat162float(h1));
    __nv_bfloat16 l2 = __float2bfloat16(v.z - __bfloat162float(h2));
    __nv_bfloat16 l3 = __float2bfloat16(v.w - __bfloat162float(h3));
    __nv_bfloat162* ph = (__nv_bfloat162*)(g_Xhi + (size_t)idx * 4);
    __nv_bfloat162* pl = (__nv_bfloat162*)(g_Xlo + (size_t)idx * 4);
    ph[0] = __nv_bfloat162(h0, h1); ph[1] = __nv_bfloat162(h2, h3);
    pl[0] = __nv_bfloat162(l0, l1); pl[1] = __nv_bfloat162(l2, l3);
}

// ---------------- weight transpose + hi/lo split into weight slot ----------------
__global__ void __launch_bounds__(256) k_cvt_w(const float* __restrict__ W, int slot) {
    __shared__ float tile[32][33];
    const size_t wb = (size_t)slot * FF * FF;
    int tx = threadIdx.x & 31, ty = threadIdx.x >> 5;
    int bn = blockIdx.x * 32, bk = blockIdx.y * 32;
    for (int r = ty; r < 32; r += 8)
        tile[r][tx] = W[(size_t)(bk + r) * FF + bn + tx];
    __syncthreads();
    for (int r = ty; r < 32; r += 8) {
        float v = tile[tx][r];
        __nv_bfloat16 h = __float2bfloat16(v);
        g_Wthi[wb + (size_t)(bn + r) * FF + bk + tx] = h;
        g_Wtlo[wb + (size_t)(bn + r) * FF + bk + tx] = __float2bfloat16(v - __bfloat162float(h));
    }
}

// ---------------- fused split-bf16 GEMM: g_B = Xhi*Whi + Xhi*Wlo + Xlo*Whi ----------------
// BM=64, BN=128, 256 threads (2x4 warp grid), 3-stage pipeline, 2 CTAs/SM.
__global__ void __launch_bounds__(256, 2) k_gemm_mma(int wslot) {
    __shared__ __align__(16) unsigned char sm[NSTG][STG_B];

    const int tid = threadIdx.x;
    const int lane = tid & 31, wid = tid >> 5;
    const int n0 = blockIdx.x * BN, m0 = blockIdx.y * BM;
    const int mbase = (wid >> 2) * 32, nbase = (wid & 3) * 32;
    const uint32_t smb = stu32(sm);
    const __nv_bfloat16* Whi = g_Wthi + (size_t)wslot * FF * FF;
    const __nv_bfloat16* Wlo = g_Wtlo + (size_t)wslot * FF * FF;

    float d[2][4][4];
#pragma unroll
    for (int i = 0; i < 2; i++)
#pragma unroll
        for (int j = 0; j < 4; j++)
#pragma unroll
            for (int q = 0; q < 4; q++) d[i][j][q] = 0.0f;

    // loaders: A (64 rows x 2 ch) by threads 0..127 ; B (128 rows x 2 ch) by all 256
    const int arow = (tid & 127) >> 1, ach = tid & 1;
    const int brow = tid >> 1, bch = tid & 1;
    auto load_tiles = [&](int it, int stg) {
        const int kb = it * BK;
        const uint32_t base = smb + stg * STG_B;
        if (tid < 128) {
            uint32_t oa = tswz(arow, ach);
            const size_t xoff = (size_t)(m0 + arow) * FF + kb + ach * 8;
            int szx = (m0 + arow) < NN ? 16 : 0;
            asm volatile("cp.async.cg.shared.global [%0], [%1], 16, %2;"
                         :: "r"(base + oa), "l"((const void*)(g_Xhi + xoff)), "r"(szx));
            asm volatile("cp.async.cg.shared.global [%0], [%1], 16, %2;"
                         :: "r"(base + A_T + oa), "l"((const void*)(g_Xlo + xoff)), "r"(szx));
        }
        uint32_t ob = tswz(brow, bch);
        const size_t woff = (size_t)(n0 + brow) * FF + kb + bch * 8;
        asm volatile("cp.async.cg.shared.global [%0], [%1], 16;"
                     :: "r"(base + 2 * A_T + ob), "l"((const void*)(Whi + woff)));
        asm volatile("cp.async.cg.shared.global [%0], [%1], 16;"
                     :: "r"(base + 2 * A_T + B_T + ob), "l"((const void*)(Wlo + woff)));
        asm volatile("cp.async.commit_group;" ::: "memory");
    };

    load_tiles(0, 0);
    load_tiles(1, 1);

    const int frow = lane & 15, fch = lane >> 4;   // fragment lane mapping
    for (int it = 0; it < NT; it++) {
        const int stg = it % NSTG;
        if (it + 2 < NT) {
            load_tiles(it + 2, (it + 2) % NSTG);
            asm volatile("cp.async.wait_group 2;" ::: "memory");
        } else if (it + 1 < NT) {
            asm volatile("cp.async.wait_group 1;" ::: "memory");
        } else {
            asm volatile("cp.async.wait_group 0;" ::: "memory");
        }
        __syncthreads();

        const uint32_t base = smb + stg * STG_B;
        uint32_t aHi[2][4], aLo[2][4], bHi[4][2], bLo[4][2];
#pragma unroll
        for (int mf = 0; mf < 2; mf++) {
            uint32_t off = tswz(mbase + mf * 16 + frow, fch);
            asm volatile("ldmatrix.sync.aligned.m8n8.x4.shared.b16 {%0,%1,%2,%3}, [%4];"
                         : "=r"(aHi[mf][0]), "=r"(aHi[mf][1]), "=r"(aHi[mf][2]), "=r"(aHi[mf][3])
                         : "r"(base + off));
            asm volatile("ldmatrix.sync.aligned.m8n8.x4.shared.b16 {%0,%1,%2,%3}, [%4];"
                         : "=r"(aLo[mf][0]), "=r"(aLo[mf][1]), "=r"(aLo[mf][2]), "=r"(aLo[mf][3])
                         : "r"(base + A_T + off));
        }
#pragma unroll
        for (int nb = 0; nb < 2; nb++) {
            uint32_t off = tswz(nbase + nb * 16 + frow, fch);
            uint32_t r0, r1, r2, r3;
            asm volatile("ldmatrix.sync.aligned.m8n8.x4.shared.b16 {%0,%1,%2,%3}, [%4];"
                         : "=r"(r0), "=r"(r1), "=r"(r2), "=r"(r3)
                         : "r"(base + 2 * A_T + off));
            bHi[nb * 2][0] = r0; bHi[nb * 2][1] = r2;
            bHi[nb * 2 + 1][0] = r1; bHi[nb * 2 + 1][1] = r3;
            asm volatile("ldmatrix.sync.aligned.m8n8.x4.shared.b16 {%0,%1,%2,%3}, [%4];"
                         : "=r"(r0), "=r"(r1), "=r"(r2), "=r"(r3)
                         : "r"(base + 2 * A_T + B_T + off));
            bLo[nb * 2][0] = r0; bLo[nb * 2][1] = r2;
            bLo[nb * 2 + 1][0] = r1; bLo[nb * 2 + 1][1] = r3;
        }

#define MMA(A, B, mf, nf)                                                         \
        asm volatile(                                                             \
            "mma.sync.aligned.m16n8k16.row.col.f32.bf16.bf16.f32 "                \
            "{%0,%1,%2,%3}, {%4,%5,%6,%7}, {%8,%9}, {%0,%1,%2,%3};"               \
            : "+f"(d[mf][nf][0]), "+f"(d[mf][nf][1]),                             \
              "+f"(d[mf][nf][2]), "+f"(d[mf][nf][3])                              \
            : "r"(A[mf][0]), "r"(A[mf][1]), "r"(A[mf][2]), "r"(A[mf][3]),         \
              "r"(B[nf][0]), "r"(B[nf][1]))
#pragma unroll
        for (int mf = 0; mf < 2; mf++)
#pragma unroll
            for (int nf = 0; nf < 4; nf++) {
                MMA(aHi, bHi, mf, nf);
                MMA(aHi, bLo, mf, nf);
                MMA(aLo, bHi, mf, nf);
            }
#undef MMA
        __syncthreads();
    }

    // epilogue: write fp32 result to g_B
    const int g = lane >> 2, tg = lane & 3;
#pragma unroll
    for (int mf = 0; mf < 2; mf++) {
        int row0 = m0 + mbase + mf * 16 + g;
        int row1 = row0 + 8;
#pragma unroll
        for (int nf = 0; nf < 4; nf++) {
            int col = n0 + nbase + nf * 8 + tg * 2;
            if (row0 < NN)
                *(float2*)(g_B + (size_t)row0 * FF + col) = make_float2(d[mf][nf][0], d[mf][nf][1]);
            if (row1 < NN)
                *(float2*)(g_B + (size_t)row1 * FF + col) = make_float2(d[mf][nf][2], d[mf][nf][3]);
        }
    }
}

// ---------------- fused aggregation (R8 exact: smem staging, unroll 4) ----------------
__global__ void __launch_bounds__(128) k_agg(const float* __restrict__ bias,
                                             int mode, float* __restrict__ extOut) {
    const float* h = g_B;
    __shared__ int   sh_src[128];
    __shared__ float sh_w[128];
    const int i = blockIdx.x;
    const int t = threadIdx.x;

    float dd = g_dis[i];
    float w0 = dd * dd;
    float4 acc = ((const float4*)(h + (size_t)i * FF))[t];
    acc.x *= w0; acc.y *= w0; acc.z *= w0; acc.w *= w0;

    const int s = g_rowptr[i], e2 = g_rowptr[i + 1];
    for (int base = s; base < e2; base += 128) {
        int m = e2 - base;
        if (m > 128) m = 128;
        if (t < m) {
            sh_src[t] = g_srcidx[base + t];
            sh_w[t]   = g_ew[base + t];
        }
        __syncthreads();
#pragma unroll 4
        for (int j = 0; j < m; j++) {
            const float4 v = ((const float4*)(h + (size_t)sh_src[j] * FF))[t];
            const float w = sh_w[j];
            acc.x += v.x * w; acc.y += v.y * w;
            acc.z += v.z * w; acc.w += v.w * w;
        }
        __syncthreads();
    }

    float4 bb = ((const float4*)bias)[t];
    acc.x += bb.x; acc.y += bb.y; acc.z += bb.z; acc.w += bb.w;

    if (mode) {
        acc.x = fmaxf(acc.x, 0.f); acc.y = fmaxf(acc.y, 0.f);
        acc.z = fmaxf(acc.z, 0.f); acc.w = fmaxf(acc.w, 0.f);
        __nv_bfloat16 h0 = __float2bfloat16(acc.x), h1 = __float2bfloat16(acc.y);
        __nv_bfloat16 h2 = __float2bfloat16(acc.z), h3 = __float2bfloat16(acc.w);
        __nv_bfloat16 l0 = __float2bfloat16(acc.x - __bfloat162float(h0));
        __nv_bfloat16 l1 = __float2bfloat16(acc.y - __bfloat162float(h1));
        __nv_bfloat16 l2 = __float2bfloat16(acc.z - __bfloat162float(h2));
        __nv_bfloat16 l3 = __float2bfloat16(acc.w - __bfloat162float(h3));
        size_t o = (size_t)i * FF + t * 4;
        __nv_bfloat162* ph = (__nv_bfloat162*)(g_Xhi + o);
        __nv_bfloat162* pl = (__nv_bfloat162*)(g_Xlo + o);
        ph[0] = __nv_bfloat162(h0, h1); ph[1] = __nv_bfloat162(h2, h3);
        pl[0] = __nv_bfloat162(l0, l1); pl[1] = __nv_bfloat162(l2, l3);
    } else {
        ((float4*)(extOut + (size_t)i * FF))[t] = acc;
    }
}

// ---------------- launcher: capture fork (s2 joins via event BEFORE any launch) ----------------
extern "C" void kernel_launch(void* const* d_in, const int* in_sizes, int n_in,
                              void* d_out, int out_size) {
    const float* x   = (const float*)d_in[0];
    const void*  ei  = d_in[1];
    const float* W1  = (const float*)d_in[2];
    const float* b1  = (const float*)d_in[3];
    const float* W2  = (const float*)d_in[4];
    const float* b2  = (const float*)d_in[5];
    const float* W3  = (const float*)d_in[6];
    const float* b3  = (const float*)d_in[7];
    float* out       = (float*)d_out;

    dim3 gemm_grid(FF / BN, (NN + BM - 1) / BM);   // (4, 157)
    dim3 cvtw_grid(16, 16);
    int cvtx_blocks = (NN * FF / 4 + 255) / 256;

    cudaStream_t s2;
    cudaEvent_t ev0, ev_g, ev_c;
    cudaStreamCreateWithFlags(&s2, cudaStreamNonBlocking);
    cudaEventCreateWithFlags(&ev0, cudaEventDisableTiming);
    cudaEventCreateWithFlags(&ev_g, cudaEventDisableTiming);
    cudaEventCreateWithFlags(&ev_c, cudaEventDisableTiming);

    // origin stream starts the graph; s2 joins via event BEFORE its first launch
    k_detect<<<41, 256>>>((const int*)ei);
    cudaEventRecord(ev0, 0);
    cudaStreamWaitEvent(s2, ev0, 0);

    // fork: edge/CSR chain on 0  ||  converter chain on s2
    k_deg_acc<<<(EE + 255) / 256, 256>>>(ei);
    k_scan<<<1, 1024>>>();
    k_fill<<<(EE + 255) / 256, 256>>>(ei);

    k_cvt_w<<<cvtw_grid, 256, 0, s2>>>(W1, 0);
    k_cvt_x<<<cvtx_blocks, 256, 0, s2>>>(x);
    cudaEventRecord(ev_c, s2);
    cudaStreamWaitEvent(0, ev_c, 0);   // join

    const float* Ws[3] = {W1, W2, W3};
    const float* bs[3] = {b1, b2, b3};
    for (int l = 0; l < 3; l++) {
        const int slot = l & 1;
        k_gemm_mma<<<gemm_grid, 256>>>(slot);
        if (l < 2) {
            // convert next layer's weights on s2, overlapped with this layer's agg
            cudaEventRecord(ev_g, 0);
            cudaStreamWaitEvent(s2, ev_g, 0);
            k_cvt_w<<<cvtw_grid, 256, 0, s2>>>(Ws[l + 1], slot ^ 1);
            cudaEventRecord(ev_c, s2);
        }
        const int mode = (l < 2) ? 1 : 0;
        float* dst = (l < 2) ? nullptr : out;
        k_agg<<<NN, 128>>>(bs[l], mode, dst);
        if (l < 2) cudaStreamWaitEvent(0, ev_c, 0);
    }

    // destroy only when NOT capturing (destroying a captured stream invalidates the graph)
    cudaStreamCaptureStatus st = cudaStreamCaptureStatusNone;
    cudaStreamIsCapturing(0, &st);
    if (st == cudaStreamCaptureStatusNone) {
        cudaStreamDestroy(s2);
        cudaEventDestroy(ev0);
        cudaEventDestroy(ev_g);
        cudaEventDestroy(ev_c);
    }
}

// round 17
// speedup vs baseline: 1.4445x; 1.0325x over previous
#include <cuda_runtime.h>
#include <cuda_bf16.h>
#include <cstdint>

#define NN 10000
#define EE 160000
#define FF 512
#define BM 64
#define BN 128
#define BK 16
#define NT 32               // 512/16 k-tiles
#define NSTG 3              // cp.async pipeline stages
// per-stage smem (bytes): Ahi 2048 | Alo 2048 | Bhi 4096 | Blo 4096 = 12288
#define A_T 2048
#define B_T 4096
#define STG_B 12288

// ---------------- scratch (__device__ globals; no allocs) ----------------
__device__ __align__(16) float g_B[NN * FF];
__device__ __align__(16) __nv_bfloat16 g_Xhi[NN * FF];
__device__ __align__(16) __nv_bfloat16 g_Xlo[NN * FF];
__device__ __align__(16) __nv_bfloat16 g_Wthi[2 * FF * FF];   // double-buffered: [slot][n][k]
__device__ __align__(16) __nv_bfloat16 g_Wtlo[2 * FF * FF];
__device__ float g_dis[NN];
__device__ int   g_deg[NN];
__device__ int   g_rowptr[NN + 1];
__device__ int   g_cur[NN];
__device__ int   g_srcidx[EE];
__device__ float g_ew[EE];
__device__ int   g_is64;

__device__ __forceinline__ uint32_t stu32(const void* p) {
    uint32_t a;
    asm("{ .reg .u64 t; cvta.to.shared.u64 t, %1; cvt.u32.u64 %0, t; }" : "=r"(a) : "l"(p));
    return a;
}

// swizzled byte offset of (row r, 16B-chunk c) in a [rows x 16] bf16 tile
__device__ __forceinline__ uint32_t tswz(int r, int c) {
    return (uint32_t)((r * 32 + c * 16) ^ (((r >> 2) & 7) << 4));
}

// ---------------- detect edge dtype + zero degree (fused) ----------------
__global__ void __launch_bounds__(256) k_detect(const int* __restrict__ ei32) {
    if (blockIdx.x < 40) {
        int i = blockIdx.x * 256 + threadIdx.x;
        if (i < NN) g_deg[i] = 0;
        return;
    }
    __shared__ int red[256];
    int t = threadIdx.x;
    int acc = 0;
    for (int w = 1 + 2 * t; w < 4096; w += 512) acc |= ei32[w];
    red[t] = acc;
    __syncthreads();
    for (int off = 128; off > 0; off >>= 1) {
        if (t < off) red[t] |= red[t + off];
        __syncthreads();
    }
    if (t == 0) g_is64 = (red[0] == 0) ? 1 : 0;
}

__device__ __forceinline__ int edge_at(const void* ei, int idx) {
    if (g_is64) return (int)((const long long*)ei)[idx];
    return ((const int*)ei)[idx];
}

// ---------------- degree accumulate ----------------
__global__ void k_deg_acc(const void* __restrict__ ei) {
    int e = blockIdx.x * 256 + threadIdx.x;
    if (e >= EE) return;
    int c = edge_at(ei, EE + e);
    if ((unsigned)c < NN) atomicAdd(&g_deg[c], 1);
}

// ---------------- scan: thread-serial x10 + one block shuffle scan ----------------
__global__ void __launch_bounds__(1024) k_scan() {
    __shared__ int wsum[32];
    const int t = threadIdx.x, lane = t & 31, w = t >> 5;
    const int i0 = t * 10;
    int loc[10];
    int tot = 0;
#pragma unroll
    for (int q = 0; q < 10; q++) {
        int i = i0 + q;
        int v = (i < NN) ? g_deg[i] : 0;
        loc[q] = tot;
        tot += v;
    }
    int s = tot;
#pragma unroll
    for (int o = 1; o < 32; o <<= 1) {
        int x = __shfl_up_sync(0xFFFFFFFFu, s, o);
        if (lane >= o) s += x;
    }
    if (lane == 31) wsum[w] = s;
    __syncthreads();
    if (w == 0) {
        int ws = wsum[lane];
#pragma unroll
        for (int o = 1; o < 32; o <<= 1) {
            int x = __shfl_up_sync(0xFFFFFFFFu, ws, o);
            if (lane >= o) ws += x;
        }
        wsum[lane] = ws;
    }
    __syncthreads();
    int base = (w > 0 ? wsum[w - 1] : 0) + s - tot;
#pragma unroll
    for (int q = 0; q < 10; q++) {
        int i = i0 + q;
        if (i < NN) {
            int excl = base + loc[q];
            g_rowptr[i] = excl;
            g_cur[i] = excl;
            g_dis[i] = rsqrtf(1.0f + (float)g_deg[i]);
        }
    }
    if (t == 1023) g_rowptr[NN] = base + tot;
}

// ---------------- CSR fill ----------------
__global__ void k_fill(const void* __restrict__ ei) {
    int e = blockIdx.x * 256 + threadIdx.x;
    if (e >= EE) return;
    int r = edge_at(ei, e);
    int c = edge_at(ei, EE + e);
    if ((unsigned)r >= NN || (unsigned)c >= NN) return;
    int pos = atomicAdd(&g_cur[c], 1);
    if ((unsigned)pos < EE) {
        g_srcidx[pos] = r;
        g_ew[pos] = g_dis[r] * g_dis[c];
    }
}

// ---------------- fp32 -> bf16 hi/lo split of the input x ----------------
__global__ void __launch_bounds__(256) k_cvt_x(const float* __restrict__ src) {
    int idx = blockIdx.x * 256 + threadIdx.x;
    if (idx >= NN * FF / 4) return;
    float4 v = ((const float4*)src)[idx];
    __nv_bfloat16 h0 = __float2bfloat16(v.x), h1 = __float2bfloat16(v.y);
    __nv_bfloat16 h2 = __float2bfloat16(v.z), h3 = __float2bfloat16(v.w);
    __nv_bfloat16 l0 = __float2bfloat16(v.x - __bfloat162float(h0));
    __nv_bfloat16 l1 = __float2bfloat16(v.y - __bfloat162float(h1));
    __nv_bfloat16 l2 = __float2bfloat16(v.z - __bfloat162float(h2));
    __nv_bfloat16 l3 = __float2bfloat16(v.w - __bfloat162float(h3));
    __nv_bfloat162* ph = (__nv_bfloat162*)(g_Xhi + (size_t)idx * 4);
    __nv_bfloat162* pl = (__nv_bfloat162*)(g_Xlo + (size_t)idx * 4);
    ph[0] = __nv_bfloat162(h0, h1); ph[1] = __nv_bfloat162(h2, h3);
    pl[0] = __nv_bfloat162(l0, l1); pl[1] = __nv_bfloat162(l2, l3);
}

// ---------------- weight transpose + hi/lo split into weight slot ----------------
__global__ void __launch_bounds__(256) k_cvt_w(const float* __restrict__ W, int slot) {
    __shared__ float tile[32][33];
    const size_t wb = (size_t)slot * FF * FF;
    int tx = threadIdx.x & 31, ty = threadIdx.x >> 5;
    int bn = blockIdx.x * 32, bk = blockIdx.y * 32;
    for (int r = ty; r < 32; r += 8)
        tile[r][tx] = W[(size_t)(bk + r) * FF + bn + tx];
    __syncthreads();
    for (int r = ty; r < 32; r += 8) {
        float v = tile[tx][r];
        __nv_bfloat16 h = __float2bfloat16(v);
        g_Wthi[wb + (size_t)(bn + r) * FF + bk + tx] = h;
        g_Wtlo[wb + (size_t)(bn + r) * FF + bk + tx] = __float2bfloat16(v - __bfloat162float(h));
    }
}

// ---------------- fused split-bf16 GEMM: g_B = Xhi*Whi + Xhi*Wlo + Xlo*Whi ----------------
// BM=64, BN=128, 256 threads (2x4 warp grid), 3-stage pipeline, 3 CTAs/SM.
__global__ void __launch_bounds__(256, 3) k_gemm_mma(int wslot) {
    __shared__ __align__(16) unsigned char sm[NSTG][STG_B];

    const int tid = threadIdx.x;
    const int lane = tid & 31, wid = tid >> 5;
    const int n0 = blockIdx.x * BN, m0 = blockIdx.y * BM;
    const int mbase = (wid >> 2) * 32, nbase = (wid & 3) * 32;
    const uint32_t smb = stu32(sm);
    const __nv_bfloat16* Whi = g_Wthi + (size_t)wslot * FF * FF;
    const __nv_bfloat16* Wlo = g_Wtlo + (size_t)wslot * FF * FF;

    float d[2][4][4];
#pragma unroll
    for (int i = 0; i < 2; i++)
#pragma unroll
        for (int j = 0; j < 4; j++)
#pragma unroll
            for (int q = 0; q < 4; q++) d[i][j][q] = 0.0f;

    // loaders: A (64 rows x 2 ch) by threads 0..127 ; B (128 rows x 2 ch) by all 256
    const int arow = (tid & 127) >> 1, ach = tid & 1;
    const int brow = tid >> 1, bch = tid & 1;
    auto load_tiles = [&](int it, int stg) {
        const int kb = it * BK;
        const uint32_t base = smb + stg * STG_B;
        if (tid < 128) {
            uint32_t oa = tswz(arow, ach);
            const size_t xoff = (size_t)(m0 + arow) * FF + kb + ach * 8;
            int szx = (m0 + arow) < NN ? 16 : 0;
            asm volatile("cp.async.cg.shared.global [%0], [%1], 16, %2;"
                         :: "r"(base + oa), "l"((const void*)(g_Xhi + xoff)), "r"(szx));
            asm volatile("cp.async.cg.shared.global [%0], [%1], 16, %2;"
                         :: "r"(base + A_T + oa), "l"((const void*)(g_Xlo + xoff)), "r"(szx));
        }
        uint32_t ob = tswz(brow, bch);
        const size_t woff = (size_t)(n0 + brow) * FF + kb + bch * 8;
        asm volatile("cp.async.cg.shared.global [%0], [%1], 16;"
                     :: "r"(base + 2 * A_T + ob), "l"((const void*)(Whi + woff)));
        asm volatile("cp.async.cg.shared.global [%0], [%1], 16;"
                     :: "r"(base + 2 * A_T + B_T + ob), "l"((const void*)(Wlo + woff)));
        asm volatile("cp.async.commit_group;" ::: "memory");
    };

    load_tiles(0, 0);
    load_tiles(1, 1);

    const int frow = lane & 15, fch = lane >> 4;   // fragment lane mapping
    for (int it = 0; it < NT; it++) {
        const int stg = it % NSTG;
        if (it + 2 < NT) {
            load_tiles(it + 2, (it + 2) % NSTG);
            asm volatile("cp.async.wait_group 2;" ::: "memory");
        } else if (it + 1 < NT) {
            asm volatile("cp.async.wait_group 1;" ::: "memory");
        } else {
            asm volatile("cp.async.wait_group 0;" ::: "memory");
        }
        __syncthreads();

        const uint32_t base = smb + stg * STG_B;
        uint32_t aHi[2][4], aLo[2][4], bHi[4][2], bLo[4][2];
#pragma unroll
        for (int mf = 0; mf < 2; mf++) {
            uint32_t off = tswz(mbase + mf * 16 + frow, fch);
            asm volatile("ldmatrix.sync.aligned.m8n8.x4.shared.b16 {%0,%1,%2,%3}, [%4];"
                         : "=r"(aHi[mf][0]), "=r"(aHi[mf][1]), "=r"(aHi[mf][2]), "=r"(aHi[mf][3])
                         : "r"(base + off));
            asm volatile("ldmatrix.sync.aligned.m8n8.x4.shared.b16 {%0,%1,%2,%3}, [%4];"
                         : "=r"(aLo[mf][0]), "=r"(aLo[mf][1]), "=r"(aLo[mf][2]), "=r"(aLo[mf][3])
                         : "r"(base + A_T + off));
        }
#pragma unroll
        for (int nb = 0; nb < 2; nb++) {
            uint32_t off = tswz(nbase + nb * 16 + frow, fch);
            uint32_t r0, r1, r2, r3;
            asm volatile("ldmatrix.sync.aligned.m8n8.x4.shared.b16 {%0,%1,%2,%3}, [%4];"
                         : "=r"(r0), "=r"(r1), "=r"(r2), "=r"(r3)
                         : "r"(base + 2 * A_T + off));
            bHi[nb * 2][0] = r0; bHi[nb * 2][1] = r2;
            bHi[nb * 2 + 1][0] = r1; bHi[nb * 2 + 1][1] = r3;
            asm volatile("ldmatrix.sync.aligned.m8n8.x4.shared.b16 {%0,%1,%2,%3}, [%4];"
                         : "=r"(r0), "=r"(r1), "=r"(r2), "=r"(r3)
                         : "r"(base + 2 * A_T + B_T + off));
            bLo[nb * 2][0] = r0; bLo[nb * 2][1] = r2;
            bLo[nb * 2 + 1][0] = r1; bLo[nb * 2 + 1][1] = r3;
        }

#define MMA(A, B, mf, nf)                                                         \
        asm volatile(                                                             \
            "mma.sync.aligned.m16n8k16.row.col.f32.bf16.bf16.f32 "                \
            "{%0,%1,%2,%3}, {%4,%5,%6,%7}, {%8,%9}, {%0,%1,%2,%3};"               \
            : "+f"(d[mf][nf][0]), "+f"(d[mf][nf][1]),                             \
              "+f"(d[mf][nf][2]), "+f"(d[mf][nf][3])                              \
            : "r"(A[mf][0]), "r"(A[mf][1]), "r"(A[mf][2]), "r"(A[mf][3]),         \
              "r"(B[nf][0]), "r"(B[nf][1]))
#pragma unroll
        for (int mf = 0; mf < 2; mf++)
#pragma unroll
            for (int nf = 0; nf < 4; nf++) {
                MMA(aHi, bHi, mf, nf);
                MMA(aHi, bLo, mf, nf);
                MMA(aLo, bHi, mf, nf);
            }
#undef MMA
        __syncthreads();
    }

    // epilogue: write fp32 result to g_B
    const int g = lane >> 2, tg = lane & 3;
#pragma unroll
    for (int mf = 0; mf < 2; mf++) {
        int row0 = m0 + mbase + mf * 16 + g;
        int row1 = row0 + 8;
#pragma unroll
        for (int nf = 0; nf < 4; nf++) {
            int col = n0 + nbase + nf * 8 + tg * 2;
            if (row0 < NN)
                *(float2*)(g_B + (size_t)row0 * FF + col) = make_float2(d[mf][nf][0], d[mf][nf][1]);
            if (row1 < NN)
                *(float2*)(g_B + (size_t)row1 * FF + col) = make_float2(d[mf][nf][2], d[mf][nf][3]);
        }
    }
}

// ---------------- fused aggregation (R8 exact: smem staging, unroll 4) ----------------
__global__ void __launch_bounds__(128) k_agg(const float* __restrict__ bias,
                                             int mode, float* __restrict__ extOut) {
    const float* h = g_B;
    __shared__ int   sh_src[128];
    __shared__ float sh_w[128];
    const int i = blockIdx.x;
    const int t = threadIdx.x;

    float dd = g_dis[i];
    float w0 = dd * dd;
    float4 acc = ((const float4*)(h + (size_t)i * FF))[t];
    acc.x *= w0; acc.y *= w0; acc.z *= w0; acc.w *= w0;

    const int s = g_rowptr[i], e2 = g_rowptr[i + 1];
    for (int base = s; base < e2; base += 128) {
        int m = e2 - base;
        if (m > 128) m = 128;
        if (t < m) {
            sh_src[t] = g_srcidx[base + t];
            sh_w[t]   = g_ew[base + t];
        }
        __syncthreads();
#pragma unroll 4
        for (int j = 0; j < m; j++) {
            const float4 v = ((const float4*)(h + (size_t)sh_src[j] * FF))[t];
            const float w = sh_w[j];
            acc.x += v.x * w; acc.y += v.y * w;
            acc.z += v.z * w; acc.w += v.w * w;
        }
        __syncthreads();
    }

    float4 bb = ((const float4*)bias)[t];
    acc.x += bb.x; acc.y += bb.y; acc.z += bb.z; acc.w += bb.w;

    if (mode) {
        acc.x = fmaxf(acc.x, 0.f); acc.y = fmaxf(acc.y, 0.f);
        acc.z = fmaxf(acc.z, 0.f); acc.w = fmaxf(acc.w, 0.f);
        __nv_bfloat16 h0 = __float2bfloat16(acc.x), h1 = __float2bfloat16(acc.y);
        __nv_bfloat16 h2 = __float2bfloat16(acc.z), h3 = __float2bfloat16(acc.w);
        __nv_bfloat16 l0 = __float2bfloat16(acc.x - __bfloat162float(h0));
        __nv_bfloat16 l1 = __float2bfloat16(acc.y - __bfloat162float(h1));
        __nv_bfloat16 l2 = __float2bfloat16(acc.z - __bfloat162float(h2));
        __nv_bfloat16 l3 = __float2bfloat16(acc.w - __bfloat162float(h3));
        size_t o = (size_t)i * FF + t * 4;
        __nv_bfloat162* ph = (__nv_bfloat162*)(g_Xhi + o);
        __nv_bfloat162* pl = (__nv_bfloat162*)(g_Xlo + o);
        ph[0] = __nv_bfloat162(h0, h1); ph[1] = __nv_bfloat162(h2, h3);
        pl[0] = __nv_bfloat162(l0, l1); pl[1] = __nv_bfloat162(l2, l3);
    } else {
        ((float4*)(extOut + (size_t)i * FF))[t] = acc;
    }
}

// ---------------- launcher: capture fork (s2 joins via event BEFORE any launch) ----------------
extern "C" void kernel_launch(void* const* d_in, const int* in_sizes, int n_in,
                              void* d_out, int out_size) {
    const float* x   = (const float*)d_in[0];
    const void*  ei  = d_in[1];
    const float* W1  = (const float*)d_in[2];
    const float* b1  = (const float*)d_in[3];
    const float* W2  = (const float*)d_in[4];
    const float* b2  = (const float*)d_in[5];
    const float* W3  = (const float*)d_in[6];
    const float* b3  = (const float*)d_in[7];
    float* out       = (float*)d_out;

    dim3 gemm_grid(FF / BN, (NN + BM - 1) / BM);   // (4, 157)
    dim3 cvtw_grid(16, 16);
    int cvtx_blocks = (NN * FF / 4 + 255) / 256;

    cudaStream_t s2;
    cudaEvent_t ev0, ev_g, ev_c;
    cudaStreamCreateWithFlags(&s2, cudaStreamNonBlocking);
    cudaEventCreateWithFlags(&ev0, cudaEventDisableTiming);
    cudaEventCreateWithFlags(&ev_g, cudaEventDisableTiming);
    cudaEventCreateWithFlags(&ev_c, cudaEventDisableTiming);

    // origin stream starts the graph; s2 joins via event BEFORE its first launch
    k_detect<<<41, 256>>>((const int*)ei);
    cudaEventRecord(ev0, 0);
    cudaStreamWaitEvent(s2, ev0, 0);

    // fork: edge/CSR chain on 0  ||  converter chain on s2
    k_deg_acc<<<(EE + 255) / 256, 256>>>(ei);
    k_scan<<<1, 1024>>>();
    k_fill<<<(EE + 255) / 256, 256>>>(ei);

    k_cvt_w<<<cvtw_grid, 256, 0, s2>>>(W1, 0);
    k_cvt_x<<<cvtx_blocks, 256, 0, s2>>>(x);
    cudaEventRecord(ev_c, s2);
    cudaStreamWaitEvent(0, ev_c, 0);   // join

    const float* Ws[3] = {W1, W2, W3};
    const float* bs[3] = {b1, b2, b3};
    for (int l = 0; l < 3; l++) {
        const int slot = l & 1;
        k_gemm_mma<<<gemm_grid, 256>>>(slot);
        if (l < 2) {
            // convert next layer's weights on s2, overlapped with this layer's agg
            cudaEventRecord(ev_g, 0);
            cudaStreamWaitEvent(s2, ev_g, 0);
            k_cvt_w<<<cvtw_grid, 256, 0, s2>>>(Ws[l + 1], slot ^ 1);
            cudaEventRecord(ev_c, s2);
        }
        const int mode = (l < 2) ? 1 : 0;
        float* dst = (l < 2) ? nullptr : out;
        k_agg<<<NN, 128>>>(bs[l], mode, dst);
        if (l < 2) cudaStreamWaitEvent(0, ev_c, 0);
    }

    // destroy only when NOT capturing (destroying a captured stream invalidates the graph)
    cudaStreamCaptureStatus st = cudaStreamCaptureStatusNone;
    cudaStreamIsCapturing(0, &st);
    if (st == cudaStreamCaptureStatusNone) {
        cudaStreamDestroy(s2);
        cudaEventDestroy(ev0);
        cudaEventDestroy(ev_g);
        cudaEventDestroy(ev_c);
    }
}